// round 16
// baseline (speedup 1.0000x reference)
#include <cuda_runtime.h>
#include <cuda_bf16.h>
#include <cstdint>
#include <cstddef>

// Problem constants
#define BATCH 8
#define SEQ   1024
#define DIM   768
#define HEADS 12
#define HDIM  64
#define ROWS  (BATCH*SEQ)        // 8192

// Scratch (no cudaMalloc allowed): ~100 MB of __device__ globals
__device__ float g_q[BATCH*HEADS*SEQ*HDIM];     // [B,H,N,64], pre-scaled by 0.125
__device__ float g_k[BATCH*HEADS*SEQ*HDIM];
__device__ float g_v[BATCH*HEADS*SEQ*HDIM];
__device__ float g_attn[ROWS*DIM];              // [B,N,768]

// ---------------------------------------------------------------------------
// Tiled SGEMM: C[M,N] = A[M,K] @ B[K,N] + bias[N]
// MODE 0: scatter epilogue into g_q/g_k/g_v (QKV GEMM, N=2304)
// MODE 1: plain store to C (projection GEMM)
// BM=BN=128, BK=16, 256 threads, 8x8 per-thread tile.
// ---------------------------------------------------------------------------
template<int MODE>
__global__ __launch_bounds__(256)
void gemm_kernel(const float* __restrict__ A,
                 const float* __restrict__ B,
                 const float* __restrict__ bias,
                 float* __restrict__ C,
                 int M, int N, int K)
{
    __shared__ float As[16][128];   // transposed A tile: As[k][m]
    __shared__ float Bs[16][128];   // Bs[k][n]

    const int tid = threadIdx.x;
    const int bx = blockIdx.x, by = blockIdx.y;
    const int tx = tid & 15;        // 0..15 (cols)
    const int ty = tid >> 4;        // 0..15 (rows)

    float acc[8][8];
#pragma unroll
    for (int i = 0; i < 8; i++)
#pragma unroll
        for (int j = 0; j < 8; j++) acc[i][j] = 0.f;

    const float* Ab = A + (size_t)by * 128 * K;
    const float* Bb = B + (size_t)bx * 128;

    for (int k0 = 0; k0 < K; k0 += 16) {
        // Load A tile 128x16 (512 float4, 2 per thread), store transposed
#pragma unroll
        for (int i = 0; i < 2; i++) {
            int f  = tid + i * 256;         // 0..511
            int ar = f >> 2;                // row 0..127
            int ac = (f & 3) << 2;          // k offset 0,4,8,12
            float4 v = *(const float4*)(Ab + (size_t)ar * K + k0 + ac);
            As[ac + 0][ar] = v.x;
            As[ac + 1][ar] = v.y;
            As[ac + 2][ar] = v.z;
            As[ac + 3][ar] = v.w;
        }
        // Load B tile 16x128 (512 float4, 2 per thread), direct
#pragma unroll
        for (int i = 0; i < 2; i++) {
            int f  = tid + i * 256;
            int br = f >> 5;                // k row 0..15
            int bc = (f & 31) << 2;         // col 0..124
            *(float4*)&Bs[br][bc] = *(const float4*)(Bb + (size_t)(k0 + br) * N + bc);
        }
        __syncthreads();

#pragma unroll
        for (int k = 0; k < 16; k++) {
            float ra[8], rb[8];
            *(float4*)&ra[0] = *(const float4*)&As[k][ty * 8];
            *(float4*)&ra[4] = *(const float4*)&As[k][ty * 8 + 4];
            *(float4*)&rb[0] = *(const float4*)&Bs[k][tx * 8];
            *(float4*)&rb[4] = *(const float4*)&Bs[k][tx * 8 + 4];
#pragma unroll
            for (int i = 0; i < 8; i++)
#pragma unroll
                for (int j = 0; j < 8; j++)
                    acc[i][j] += ra[i] * rb[j];
        }
        __syncthreads();
    }

    // Epilogue
#pragma unroll
    for (int i = 0; i < 8; i++) {
        const int row = by * 128 + ty * 8 + i;
        const int b   = row >> 10;          // / SEQ
        const int n   = row & 1023;
#pragma unroll
        for (int j4 = 0; j4 < 8; j4 += 4) {
            const int col = bx * 128 + tx * 8 + j4;
            float4 bv = *(const float4*)(bias + col);
            float4 v;
            v.x = acc[i][j4 + 0] + bv.x;
            v.y = acc[i][j4 + 1] + bv.y;
            v.z = acc[i][j4 + 2] + bv.z;
            v.w = acc[i][j4 + 3] + bv.w;
            if (MODE == 0) {
                // col = t*768 + h*64 + d   (4 consecutive cols never cross t/h)
                const int t   = col / 768;
                const int rem = col - t * 768;
                const int h   = rem >> 6;
                const int d   = rem & 63;
                const size_t idx = (((size_t)b * HEADS + h) * SEQ + n) * HDIM + d;
                if (t == 0) {
                    v.x *= 0.125f; v.y *= 0.125f; v.z *= 0.125f; v.w *= 0.125f;
                    *(float4*)(g_q + idx) = v;
                } else if (t == 1) {
                    *(float4*)(g_k + idx) = v;
                } else {
                    *(float4*)(g_v + idx) = v;
                }
            } else {
                *(float4*)(C + (size_t)row * N + col) = v;
            }
        }
    }
}

// ---------------------------------------------------------------------------
// Flash attention, fp32. Grid: (SEQ/128, B*H). 128 threads, 1 thread = 1 query
// row. Online softmax over 32-key tiles in smem. Q pre-scaled by 1/sqrt(64).
// Writes g_attn[b, n, h*64 + d].
// ---------------------------------------------------------------------------
__global__ __launch_bounds__(128)
void attn_kernel()
{
    const int bh  = blockIdx.y;                 // 0..95
    const int b   = bh / HEADS;
    const int h   = bh - b * HEADS;
    const int row = blockIdx.x * 128 + threadIdx.x;   // query index in [0,1024)

    const float* Qp    = g_q + ((size_t)bh * SEQ + row) * HDIM;
    const float* Kbase = g_k + (size_t)bh * SEQ * HDIM;
    const float* Vbase = g_v + (size_t)bh * SEQ * HDIM;

    __shared__ float Ks[32][64];
    __shared__ float Vs[32][64];

    float q[64], o[64];
#pragma unroll
    for (int d = 0; d < 64; d += 4)
        *(float4*)&q[d] = *(const float4*)(Qp + d);
#pragma unroll
    for (int d = 0; d < 64; d++) o[d] = 0.f;

    float m = -1e30f, l = 0.f;

    for (int kt = 0; kt < SEQ; kt += 32) {
        // Cooperative load: 32x64 floats = 512 float4; 4 per thread; coalesced
        {
            const int t = threadIdx.x;
#pragma unroll
            for (int i = 0; i < 4; i++) {
                int f = t + i * 128;            // 0..511
                int r = f >> 4;                 // 0..31
                int c = (f & 15) << 2;          // 0..60
                *(float4*)&Ks[r][c] = *(const float4*)(Kbase + (size_t)(kt + r) * HDIM + c);
                *(float4*)&Vs[r][c] = *(const float4*)(Vbase + (size_t)(kt + r) * HDIM + c);
            }
        }
        __syncthreads();

        // Scores for 32 keys (all smem reads warp-uniform -> broadcast)
        float s[32];
        float mx = m;
#pragma unroll
        for (int j = 0; j < 32; j++) {
            float a0 = 0.f, a1 = 0.f, a2 = 0.f, a3 = 0.f;
#pragma unroll
            for (int d = 0; d < 64; d += 4) {
                float4 kv = *(const float4*)&Ks[j][d];
                a0 += q[d + 0] * kv.x;
                a1 += q[d + 1] * kv.y;
                a2 += q[d + 2] * kv.z;
                a3 += q[d + 3] * kv.w;
            }
            float sj = (a0 + a1) + (a2 + a3);
            s[j] = sj;
            mx = fmaxf(mx, sj);
        }

        // Online softmax rescale
        const float scale = __expf(m - mx);
        l *= scale;
#pragma unroll
        for (int d = 0; d < 64; d++) o[d] *= scale;

        // P @ V
#pragma unroll
        for (int j = 0; j < 32; j++) {
            const float p = __expf(s[j] - mx);
            l += p;
#pragma unroll
            for (int d = 0; d < 64; d += 4) {
                float4 vv = *(const float4*)&Vs[j][d];
                o[d + 0] += p * vv.x;
                o[d + 1] += p * vv.y;
                o[d + 2] += p * vv.z;
                o[d + 3] += p * vv.w;
            }
        }
        m = mx;
        __syncthreads();
    }

    const float inv = 1.f / l;
    float* op = g_attn + ((size_t)b * SEQ + row) * DIM + h * HDIM;
#pragma unroll
    for (int d = 0; d < 64; d += 4) {
        float4 vv;
        vv.x = o[d + 0] * inv;
        vv.y = o[d + 1] * inv;
        vv.z = o[d + 2] * inv;
        vv.w = o[d + 3] * inv;
        *(float4*)(op + d) = vv;
    }
}

// ---------------------------------------------------------------------------
// Launch: QKV GEMM -> flash attention -> projection GEMM
// Inputs (metadata order): x, qkv_w, qkv_b, proj_w, proj_b
// ---------------------------------------------------------------------------
extern "C" void kernel_launch(void* const* d_in, const int* in_sizes, int n_in,
                              void* d_out, int out_size)
{
    const float* x      = (const float*)d_in[0];
    const float* qkv_w  = (const float*)d_in[1];
    const float* qkv_b  = (const float*)d_in[2];
    const float* proj_w = (const float*)d_in[3];
    const float* proj_b = (const float*)d_in[4];
    float* out = (float*)d_out;

    void* attn_ptr = nullptr;
    cudaGetSymbolAddress(&attn_ptr, g_attn);

    // 1) qkv = x @ qkv_w + qkv_b, scattered to g_q (x0.125) / g_k / g_v
    {
        dim3 grid(3 * DIM / 128, ROWS / 128);   // (18, 64)
        gemm_kernel<0><<<grid, 256>>>(x, qkv_w, qkv_b, out, ROWS, 3 * DIM, DIM);
    }
    // 2) flash attention -> g_attn [B,N,768]
    {
        dim3 grid(SEQ / 128, BATCH * HEADS);    // (8, 96)
        attn_kernel<<<grid, 128>>>();
    }
    // 3) out = g_attn @ proj_w + proj_b
    {
        dim3 grid(DIM / 128, ROWS / 128);       // (6, 64)
        gemm_kernel<1><<<grid, 256>>>((const float*)attn_ptr, proj_w, proj_b,
                                      out, ROWS, DIM, DIM);
    }
}

// round 17
// speedup vs baseline: 1.0055x; 1.0055x over previous
#include <cuda_runtime.h>
#include <cuda_bf16.h>
#include <cstdint>
#include <cstddef>

// Problem constants
#define BATCH 8
#define SEQ   1024
#define DIM   768
#define HEADS 12
#define HDIM  64
#define ROWS  (BATCH*SEQ)        // 8192

// Scratch (no cudaMalloc allowed): ~100 MB of __device__ globals
__device__ float g_q[BATCH*HEADS*SEQ*HDIM];     // [B,H,N,64], pre-scaled by 0.125
__device__ float g_k[BATCH*HEADS*SEQ*HDIM];
__device__ float g_v[BATCH*HEADS*SEQ*HDIM];
__device__ float g_attn[ROWS*DIM];              // [B,N,768]

// ---------------------------------------------------------------------------
// Tiled SGEMM: C[M,N] = A[M,K] @ B[K,N] + bias[N]
// MODE 0: scatter epilogue into g_q/g_k/g_v (QKV GEMM, N=2304)
// MODE 1: plain store to C (projection GEMM)
// BM=BN=128, BK=16, 256 threads, 8x8 per-thread tile.
// ---------------------------------------------------------------------------
template<int MODE>
__global__ __launch_bounds__(256)
void gemm_kernel(const float* __restrict__ A,
                 const float* __restrict__ B,
                 const float* __restrict__ bias,
                 float* __restrict__ C,
                 int M, int N, int K)
{
    __shared__ float As[16][128];   // transposed A tile: As[k][m]
    __shared__ float Bs[16][128];   // Bs[k][n]

    const int tid = threadIdx.x;
    const int bx = blockIdx.x, by = blockIdx.y;
    const int tx = tid & 15;        // 0..15 (cols)
    const int ty = tid >> 4;        // 0..15 (rows)

    float acc[8][8];
#pragma unroll
    for (int i = 0; i < 8; i++)
#pragma unroll
        for (int j = 0; j < 8; j++) acc[i][j] = 0.f;

    const float* Ab = A + (size_t)by * 128 * K;
    const float* Bb = B + (size_t)bx * 128;

    for (int k0 = 0; k0 < K; k0 += 16) {
        // Load A tile 128x16 (512 float4, 2 per thread), store transposed
#pragma unroll
        for (int i = 0; i < 2; i++) {
            int f  = tid + i * 256;         // 0..511
            int ar = f >> 2;                // row 0..127
            int ac = (f & 3) << 2;          // k offset 0,4,8,12
            float4 v = *(const float4*)(Ab + (size_t)ar * K + k0 + ac);
            As[ac + 0][ar] = v.x;
            As[ac + 1][ar] = v.y;
            As[ac + 2][ar] = v.z;
            As[ac + 3][ar] = v.w;
        }
        // Load B tile 16x128 (512 float4, 2 per thread), direct
#pragma unroll
        for (int i = 0; i < 2; i++) {
            int f  = tid + i * 256;
            int br = f >> 5;                // k row 0..15
            int bc = (f & 31) << 2;         // col 0..124
            *(float4*)&Bs[br][bc] = *(const float4*)(Bb + (size_t)(k0 + br) * N + bc);
        }
        __syncthreads();

#pragma unroll
        for (int k = 0; k < 16; k++) {
            float ra[8], rb[8];
            *(float4*)&ra[0] = *(const float4*)&As[k][ty * 8];
            *(float4*)&ra[4] = *(const float4*)&As[k][ty * 8 + 4];
            *(float4*)&rb[0] = *(const float4*)&Bs[k][tx * 8];
            *(float4*)&rb[4] = *(const float4*)&Bs[k][tx * 8 + 4];
#pragma unroll
            for (int i = 0; i < 8; i++)
#pragma unroll
                for (int j = 0; j < 8; j++)
                    acc[i][j] += ra[i] * rb[j];
        }
        __syncthreads();
    }

    // Epilogue
#pragma unroll
    for (int i = 0; i < 8; i++) {
        const int row = by * 128 + ty * 8 + i;
        const int b   = row >> 10;          // / SEQ
        const int n   = row & 1023;
#pragma unroll
        for (int j4 = 0; j4 < 8; j4 += 4) {
            const int col = bx * 128 + tx * 8 + j4;
            float4 bv = *(const float4*)(bias + col);
            float4 v;
            v.x = acc[i][j4 + 0] + bv.x;
            v.y = acc[i][j4 + 1] + bv.y;
            v.z = acc[i][j4 + 2] + bv.z;
            v.w = acc[i][j4 + 3] + bv.w;
            if (MODE == 0) {
                // col = t*768 + h*64 + d   (4 consecutive cols never cross t/h)
                const int t   = col / 768;
                const int rem = col - t * 768;
                const int h   = rem >> 6;
                const int d   = rem & 63;
                const size_t idx = (((size_t)b * HEADS + h) * SEQ + n) * HDIM + d;
                if (t == 0) {
                    v.x *= 0.125f; v.y *= 0.125f; v.z *= 0.125f; v.w *= 0.125f;
                    *(float4*)(g_q + idx) = v;
                } else if (t == 1) {
                    *(float4*)(g_k + idx) = v;
                } else {
                    *(float4*)(g_v + idx) = v;
                }
            } else {
                *(float4*)(C + (size_t)row * N + col) = v;
            }
        }
    }
}

// ---------------------------------------------------------------------------
// Flash attention, fp32. Grid: (SEQ/128, B*H). 128 threads, 1 thread = 1 query
// row. Online softmax over 32-key tiles in smem. Q pre-scaled by 1/sqrt(64).
// Writes g_attn[b, n, h*64 + d].
// ---------------------------------------------------------------------------
__global__ __launch_bounds__(128)
void attn_kernel()
{
    const int bh  = blockIdx.y;                 // 0..95
    const int b   = bh / HEADS;
    const int h   = bh - b * HEADS;
    const int row = blockIdx.x * 128 + threadIdx.x;   // query index in [0,1024)

    const float* Qp    = g_q + ((size_t)bh * SEQ + row) * HDIM;
    const float* Kbase = g_k + (size_t)bh * SEQ * HDIM;
    const float* Vbase = g_v + (size_t)bh * SEQ * HDIM;

    __shared__ float Ks[32][64];
    __shared__ float Vs[32][64];

    float q[64], o[64];
#pragma unroll
    for (int d = 0; d < 64; d += 4)
        *(float4*)&q[d] = *(const float4*)(Qp + d);
#pragma unroll
    for (int d = 0; d < 64; d++) o[d] = 0.f;

    float m = -1e30f, l = 0.f;

    for (int kt = 0; kt < SEQ; kt += 32) {
        // Cooperative load: 32x64 floats = 512 float4; 4 per thread; coalesced
        {
            const int t = threadIdx.x;
#pragma unroll
            for (int i = 0; i < 4; i++) {
                int f = t + i * 128;            // 0..511
                int r = f >> 4;                 // 0..31
                int c = (f & 15) << 2;          // 0..60
                *(float4*)&Ks[r][c] = *(const float4*)(Kbase + (size_t)(kt + r) * HDIM + c);
                *(float4*)&Vs[r][c] = *(const float4*)(Vbase + (size_t)(kt + r) * HDIM + c);
            }
        }
        __syncthreads();

        // Scores for 32 keys (all smem reads warp-uniform -> broadcast)
        float s[32];
        float mx = m;
#pragma unroll
        for (int j = 0; j < 32; j++) {
            float a0 = 0.f, a1 = 0.f, a2 = 0.f, a3 = 0.f;
#pragma unroll
            for (int d = 0; d < 64; d += 4) {
                float4 kv = *(const float4*)&Ks[j][d];
                a0 += q[d + 0] * kv.x;
                a1 += q[d + 1] * kv.y;
                a2 += q[d + 2] * kv.z;
                a3 += q[d + 3] * kv.w;
            }
            float sj = (a0 + a1) + (a2 + a3);
            s[j] = sj;
            mx = fmaxf(mx, sj);
        }

        // Online softmax rescale
        const float scale = __expf(m - mx);
        l *= scale;
#pragma unroll
        for (int d = 0; d < 64; d++) o[d] *= scale;

        // P @ V
#pragma unroll
        for (int j = 0; j < 32; j++) {
            const float p = __expf(s[j] - mx);
            l += p;
#pragma unroll
            for (int d = 0; d < 64; d += 4) {
                float4 vv = *(const float4*)&Vs[j][d];
                o[d + 0] += p * vv.x;
                o[d + 1] += p * vv.y;
                o[d + 2] += p * vv.z;
                o[d + 3] += p * vv.w;
            }
        }
        m = mx;
        __syncthreads();
    }

    const float inv = 1.f / l;
    float* op = g_attn + ((size_t)b * SEQ + row) * DIM + h * HDIM;
#pragma unroll
    for (int d = 0; d < 64; d += 4) {
        float4 vv;
        vv.x = o[d + 0] * inv;
        vv.y = o[d + 1] * inv;
        vv.z = o[d + 2] * inv;
        vv.w = o[d + 3] * inv;
        *(float4*)(op + d) = vv;
    }
}

// ---------------------------------------------------------------------------
// Launch: QKV GEMM -> flash attention -> projection GEMM
// Inputs (metadata order): x, qkv_w, qkv_b, proj_w, proj_b
// ---------------------------------------------------------------------------
extern "C" void kernel_launch(void* const* d_in, const int* in_sizes, int n_in,
                              void* d_out, int out_size)
{
    const float* x      = (const float*)d_in[0];
    const float* qkv_w  = (const float*)d_in[1];
    const float* qkv_b  = (const float*)d_in[2];
    const float* proj_w = (const float*)d_in[3];
    const float* proj_b = (const float*)d_in[4];
    float* out = (float*)d_out;

    void* attn_ptr = nullptr;
    cudaGetSymbolAddress(&attn_ptr, g_attn);

    // 1) qkv = x @ qkv_w + qkv_b, scattered to g_q (x0.125) / g_k / g_v
    {
        dim3 grid(3 * DIM / 128, ROWS / 128);   // (18, 64)
        gemm_kernel<0><<<grid, 256>>>(x, qkv_w, qkv_b, out, ROWS, 3 * DIM, DIM);
    }
    // 2) flash attention -> g_attn [B,N,768]
    {
        dim3 grid(SEQ / 128, BATCH * HEADS);    // (8, 96)
        attn_kernel<<<grid, 128>>>();
    }
    // 3) out = g_attn @ proj_w + proj_b
    {
        dim3 grid(DIM / 128, ROWS / 128);       // (6, 64)
        gemm_kernel<1><<<grid, 256>>>((const float*)attn_ptr, proj_w, proj_b,
                                      out, ROWS, DIM, DIM);
    }
}